// round 4
// baseline (speedup 1.0000x reference)
#include <cuda_runtime.h>
#include <cuda_fp16.h>
#include <math.h>

#define NN 4096
#define DD 64
#define BIGF 1e30f
#define NSTRIP 32          // strips of 128 columns, 1 warp each
#define SCOLS 128
#define TSTEPS 2080        // last active step = 4096/2-1+31 = 2078; mult of 4
#define FULLM 0xffffffffu

// Static device scratch
__device__ __half g_cost[(size_t)NN * NN];                 // 32 MB fp16 cost matrix
__device__ float  g_nx[NN];
__device__ float  g_ny[NN];
__device__ __align__(256) float g_bnd[NSTRIP * NN + 64];   // right-col boundary per strip
__device__ int    g_flag[NSTRIP];                          // rows published per strip

__device__ __forceinline__ int ld_acq(const int* p) {
    int v;
    asm volatile("ld.acquire.gpu.global.b32 %0, [%1];" : "=r"(v) : "l"(p) : "memory");
    return v;
}
__device__ __forceinline__ int ld_rlx(const int* p) {
    int v;
    asm volatile("ld.relaxed.gpu.global.b32 %0, [%1];" : "=r"(v) : "l"(p) : "memory");
    return v;
}
__device__ __forceinline__ void st_rel(int* p, int v) {
    asm volatile("st.release.gpu.global.b32 [%0], %1;" :: "l"(p), "r"(v) : "memory");
}

// ---------------------------------------------------------------------------
__global__ void reset_kernel() {
    if (threadIdx.x < NSTRIP) g_flag[threadIdx.x] = 0;
}

// ---------------------------------------------------------------------------
__global__ void norms_kernel(const float* __restrict__ x, const float* __restrict__ y) {
    int i = blockIdx.x * blockDim.x + threadIdx.x;
    if (i < NN) {
        const float* p = x + (size_t)i * DD;
        float s = 0.f;
        #pragma unroll
        for (int k = 0; k < DD; k++) s += p[k] * p[k];
        g_nx[i] = s;
    } else if (i < 2 * NN) {
        int j = i - NN;
        const float* p = y + (size_t)j * DD;
        float s = 0.f;
        #pragma unroll
        for (int k = 0; k < DD; k++) s += p[k] * p[k];
        g_ny[j] = s;
    }
}

// ---------------------------------------------------------------------------
// Cost matrix: 64x64 tile per block, 64 threads, 8x8 per thread.
// ---------------------------------------------------------------------------
__global__ void __launch_bounds__(64) cost_kernel(const float* __restrict__ x,
                                                  const float* __restrict__ y) {
    __shared__ float xs[64][65];
    __shared__ float ys[64][65];

    const int I0 = blockIdx.y * 64;
    const int J0 = blockIdx.x * 64;
    const int tid = threadIdx.x;       // 0..63

    #pragma unroll 4
    for (int it = 0; it < 16; it++) {              // 16*64 float4 = 4096 floats
        int idx = (it * 64 + tid) * 4;
        int r = idx >> 6, k = idx & 63;
        float4 vx = *(const float4*)(x + (size_t)(I0 + r) * DD + k);
        float4 vy = *(const float4*)(y + (size_t)(J0 + r) * DD + k);
        xs[r][k] = vx.x; xs[r][k+1] = vx.y; xs[r][k+2] = vx.z; xs[r][k+3] = vx.w;
        ys[r][k] = vy.x; ys[r][k+1] = vy.y; ys[r][k+2] = vy.z; ys[r][k+3] = vy.w;
    }
    __syncthreads();

    const int tx = tid & 7, ty = tid >> 3;
    const int r0 = ty * 8, c0 = tx * 8;

    float acc[8][8];
    #pragma unroll
    for (int a = 0; a < 8; a++)
        #pragma unroll
        for (int b = 0; b < 8; b++) acc[a][b] = 0.f;

    #pragma unroll 4
    for (int k = 0; k < DD; k++) {
        float ra[8], rb[8];
        #pragma unroll
        for (int a = 0; a < 8; a++) ra[a] = xs[r0 + a][k];
        #pragma unroll
        for (int b = 0; b < 8; b++) rb[b] = ys[c0 + b][k];
        #pragma unroll
        for (int a = 0; a < 8; a++)
            #pragma unroll
            for (int b = 0; b < 8; b++) acc[a][b] = fmaf(ra[a], rb[b], acc[a][b]);
    }

    float nyv[8];
    #pragma unroll
    for (int b = 0; b < 8; b++) nyv[b] = g_ny[J0 + c0 + b];

    #pragma unroll
    for (int a = 0; a < 8; a++) {
        float nx = g_nx[I0 + r0 + a];
        __half2 h[4];
        #pragma unroll
        for (int b2 = 0; b2 < 4; b2++) {
            float s0 = nx + nyv[2*b2]   - 2.0f * acc[a][2*b2];
            float s1 = nx + nyv[2*b2+1] - 2.0f * acc[a][2*b2+1];
            float e0 = sqrtf(fmaxf(s0, 1e-12f));
            float e1 = sqrtf(fmaxf(s1, 1e-12f));
            h[b2] = __floats2half2_rn(e0, e1);
        }
        uint4 pk;
        pk.x = *(unsigned int*)&h[0];
        pk.y = *(unsigned int*)&h[1];
        pk.z = *(unsigned int*)&h[2];
        pk.w = *(unsigned int*)&h[3];
        *(uint4*)(g_cost + (size_t)(I0 + r0 + a) * NN + (J0 + c0)) = pk;
    }
}

// ---------------------------------------------------------------------------
// Persistent DTW: 32 strips (1 warp each), lane owns 4 cols, 2 rows per step.
// Boundary handoff: lane31 release-publishes 2 rows per step; consumer lane0
// prefetches boundary float4s one 4-step block ahead with relaxed flag
// prefetch + acq_rel fence (no L2 poll on the steady-state critical path).
// ---------------------------------------------------------------------------
__global__ void __launch_bounds__(32, 1) dtw_kernel(float* __restrict__ out) {
    const int w = blockIdx.x;
    const int lane = threadIdx.x;
    const int c0 = w * SCOLS + 4 * lane;
    const __half* gp = g_cost;
    const bool isl0 = (lane == 0);

    float t1_0 = BIGF, t1_1 = BIGF, t1_2 = BIGF, t1_3 = BIGF;
    float v30 = BIGF, v31 = BIGF, dg = BIGF;
    if (w == 0 && isl0) dg = -__half2float(g_cost[0]);   // virtual corner

    float* bndW = g_bnd + (size_t)w * NN;
    const float* bndL = g_bnd + (size_t)(w > 0 ? w - 1 : 0) * NN;
    int* flagW = &g_flag[w];
    const int* flagL = &g_flag[w > 0 ? w - 1 : 0];
    int fpre = 0;
    float4 bb0C = make_float4(BIGF, BIGF, BIGF, BIGF), bb1C = bb0C;
    float4 bb0N = bb0C, bb1N = bb1C;

    // initial boundary block (rows 0..7) for w>0
    if (w > 0 && isl0) {
        while (ld_acq(flagL) < 8) { }
        bb0C = __ldcg((const float4*)(bndL + 0));
        bb1C = __ldcg((const float4*)(bndL + 4));
        fpre = ld_rlx(flagL);
    }

    // cost double-buffer: 8 uint2 (4 halfs each) = 8 rows of my 4 cols
    uint2 cbN[8], cbC[8];
    {
        int rb = -2 * lane;
        #pragma unroll
        for (int j = 0; j < 8; j++) {
            int r = rb + j; r = r < 0 ? 0 : (r > NN - 1 ? NN - 1 : r);
            cbN[j] = *(const uint2*)(gp + (size_t)r * NN + c0);
        }
    }

    for (int tb = 0; tb < TSTEPS; tb += 4) {
        #pragma unroll
        for (int j = 0; j < 8; j++) cbC[j] = cbN[j];
        {
            int rb = 2 * (tb + 4 - lane);
            #pragma unroll
            for (int j = 0; j < 8; j++) {
                int r = rb + j; r = r < 0 ? 0 : (r > NN - 1 ? NN - 1 : r);
                cbN[j] = *(const uint2*)(gp + (size_t)r * NN + c0);
            }
        }

        // prefetch NEXT block's boundary (rows 2tb+8..2tb+15), overlapped
        if (w > 0 && isl0 && 2 * (tb + 4) < NN) {
            const int need = 2 * tb + 16;
            int f = fpre;
            while (f < need) f = ld_rlx(flagL);
            asm volatile("fence.acq_rel.gpu;" ::: "memory");
            bb0N = __ldcg((const float4*)(bndL + 2 * tb + 8));
            bb1N = __ldcg((const float4*)(bndL + 2 * tb + 12));
            fpre = ld_rlx(flagL);     // for next block's check (~4 steps away)
        }

        const int rb0 = 2 * (tb - lane);

#define DTW_STEP(K, BL0, BL1)                                                 \
        {                                                                     \
            const int r0 = rb0 + 2 * (K);                                     \
            float L0 = __shfl_up_sync(FULLM, v30, 1);                         \
            float L1 = __shfl_up_sync(FULLM, v31, 1);                         \
            if (isl0) { L0 = (w == 0) ? BIGF : (BL0);                         \
                        L1 = (w == 0) ? BIGF : (BL1); }                       \
            float2 ca = __half22float2(*(const __half2*)&cbC[2*(K)].x);       \
            float2 cb = __half22float2(*(const __half2*)&cbC[2*(K)].y);       \
            float2 cc = __half22float2(*(const __half2*)&cbC[2*(K)+1].x);     \
            float2 cd = __half22float2(*(const __half2*)&cbC[2*(K)+1].y);     \
            const float c00=ca.x, c01=ca.y, c02=cb.x, c03=cb.y;               \
            const float c10=cc.x, c11=cc.y, c12=cd.x, c13=cd.y;               \
            float p0 = fminf(fmaf(2.f, c00, dg  ), t1_0 + c00);               \
            float p1 = fminf(fmaf(2.f, c01, t1_0), t1_1 + c01);               \
            float p2 = fminf(fmaf(2.f, c02, t1_1), t1_2 + c02);               \
            float p3 = fminf(fmaf(2.f, c03, t1_2), t1_3 + c03);               \
            float n00 = fminf(p0, L0  + c00);                                 \
            float n01 = fminf(p1, n00 + c01);                                 \
            float n02 = fminf(p2, n01 + c02);                                 \
            float n03 = fminf(p3, n02 + c03);                                 \
            float q0 = fminf(fmaf(2.f, c10, L0 ), n00 + c10);                 \
            float q1 = fminf(fmaf(2.f, c11, n00), n01 + c11);                 \
            float q2 = fminf(fmaf(2.f, c12, n01), n02 + c12);                 \
            float q3 = fminf(fmaf(2.f, c13, n02), n03 + c13);                 \
            float n10 = fminf(q0, L1  + c10);                                 \
            float n11 = fminf(q1, n10 + c11);                                 \
            float n12 = fminf(q2, n11 + c12);                                 \
            float n13 = fminf(q3, n12 + c13);                                 \
            if ((unsigned)r0 < NN) {                                          \
                t1_0 = n10; t1_1 = n11; t1_2 = n12; t1_3 = n13;               \
                v30 = n03; v31 = n13;                                         \
                if (lane == 31) {                                             \
                    *(float2*)(bndW + r0) = make_float2(n03, n13);            \
                    st_rel(flagW, r0 + 2);                                    \
                    if (w == NSTRIP - 1 && r0 == NN - 2) out[0] = n13;        \
                }                                                             \
            }                                                                 \
            dg = L1;                                                          \
        }

        DTW_STEP(0, bb0C.x, bb0C.y)
        DTW_STEP(1, bb0C.z, bb0C.w)
        DTW_STEP(2, bb1C.x, bb1C.y)
        DTW_STEP(3, bb1C.z, bb1C.w)
#undef DTW_STEP

        bb0C = bb0N; bb1C = bb1N;
    }
}

// ---------------------------------------------------------------------------
extern "C" void kernel_launch(void* const* d_in, const int* in_sizes, int n_in,
                              void* d_out, int out_size) {
    const float* x = (const float*)d_in[0];
    const float* y = (const float*)d_in[1];
    float* out = (float*)d_out;

    reset_kernel<<<1, 32>>>();
    norms_kernel<<<(2 * NN + 511) / 512, 512>>>(x, y);
    cost_kernel<<<dim3(NN / 64, NN / 64), 64>>>(x, y);
    dtw_kernel<<<NSTRIP, 32>>>(out);
}

// round 8
// speedup vs baseline: 1.4920x; 1.4920x over previous
#include <cuda_runtime.h>
#include <cuda_fp16.h>
#include <math.h>

#define NN 4096
#define DD 64
#define BIGF 1e30f
#define NSTRIP 32          // strips of 128 columns, 1 warp each
#define SCOLS 128
#define TSTEPS 2080        // last active step = 4096/2-1+31 = 2078; mult of 4
#define FULLM 0xffffffffu

// Static device scratch
__device__ __half g_cost[(size_t)NN * NN];                 // 32 MB fp16 cost matrix
__device__ float  g_nx[NN];
__device__ float  g_ny[NN];
__device__ __align__(256) float g_bnd[NSTRIP * NN];        // right-col boundary per strip
__device__ int    g_flag[NSTRIP];                          // rows published per strip

// ---------------------------------------------------------------------------
__global__ void reset_kernel() {
    if (threadIdx.x < NSTRIP) g_flag[threadIdx.x] = 0;
}

// ---------------------------------------------------------------------------
__global__ void norms_kernel(const float* __restrict__ x, const float* __restrict__ y) {
    int i = blockIdx.x * blockDim.x + threadIdx.x;
    if (i < NN) {
        const float* p = x + (size_t)i * DD;
        float s = 0.f;
        #pragma unroll
        for (int k = 0; k < DD; k++) s += p[k] * p[k];
        g_nx[i] = s;
    } else if (i < 2 * NN) {
        int j = i - NN;
        const float* p = y + (size_t)j * DD;
        float s = 0.f;
        #pragma unroll
        for (int k = 0; k < DD; k++) s += p[k] * p[k];
        g_ny[j] = s;
    }
}

// ---------------------------------------------------------------------------
// Cost matrix: 64x64 tile per block, 64 threads, 8x8 per thread.
// ---------------------------------------------------------------------------
__global__ void __launch_bounds__(64) cost_kernel(const float* __restrict__ x,
                                                  const float* __restrict__ y) {
    __shared__ float xs[64][65];
    __shared__ float ys[64][65];

    const int I0 = blockIdx.y * 64;
    const int J0 = blockIdx.x * 64;
    const int tid = threadIdx.x;       // 0..63

    #pragma unroll 4
    for (int it = 0; it < 16; it++) {              // 16*64 float4 = 4096 floats
        int idx = (it * 64 + tid) * 4;
        int r = idx >> 6, k = idx & 63;
        float4 vx = *(const float4*)(x + (size_t)(I0 + r) * DD + k);
        float4 vy = *(const float4*)(y + (size_t)(J0 + r) * DD + k);
        xs[r][k] = vx.x; xs[r][k+1] = vx.y; xs[r][k+2] = vx.z; xs[r][k+3] = vx.w;
        ys[r][k] = vy.x; ys[r][k+1] = vy.y; ys[r][k+2] = vy.z; ys[r][k+3] = vy.w;
    }
    __syncthreads();

    const int tx = tid & 7, ty = tid >> 3;
    const int r0 = ty * 8, c0 = tx * 8;

    float acc[8][8];
    #pragma unroll
    for (int a = 0; a < 8; a++)
        #pragma unroll
        for (int b = 0; b < 8; b++) acc[a][b] = 0.f;

    #pragma unroll 4
    for (int k = 0; k < DD; k++) {
        float ra[8], rb[8];
        #pragma unroll
        for (int a = 0; a < 8; a++) ra[a] = xs[r0 + a][k];
        #pragma unroll
        for (int b = 0; b < 8; b++) rb[b] = ys[c0 + b][k];
        #pragma unroll
        for (int a = 0; a < 8; a++)
            #pragma unroll
            for (int b = 0; b < 8; b++) acc[a][b] = fmaf(ra[a], rb[b], acc[a][b]);
    }

    float nyv[8];
    #pragma unroll
    for (int b = 0; b < 8; b++) nyv[b] = g_ny[J0 + c0 + b];

    #pragma unroll
    for (int a = 0; a < 8; a++) {
        float nx = g_nx[I0 + r0 + a];
        __half2 h[4];
        #pragma unroll
        for (int b2 = 0; b2 < 4; b2++) {
            float s0 = nx + nyv[2*b2]   - 2.0f * acc[a][2*b2];
            float s1 = nx + nyv[2*b2+1] - 2.0f * acc[a][2*b2+1];
            float e0 = sqrtf(fmaxf(s0, 1e-12f));
            float e1 = sqrtf(fmaxf(s1, 1e-12f));
            h[b2] = __floats2half2_rn(e0, e1);
        }
        uint4 pk;
        pk.x = *(unsigned int*)&h[0];
        pk.y = *(unsigned int*)&h[1];
        pk.z = *(unsigned int*)&h[2];
        pk.w = *(unsigned int*)&h[3];
        *(uint4*)(g_cost + (size_t)(I0 + r0 + a) * NN + (J0 + c0)) = pk;
    }
}

// ---------------------------------------------------------------------------
// Persistent DTW: 32 strips (1 warp each), lane owns 4 cols, 2 rows per step.
// Sync = round-2 proven pattern: producer lane31 plain-stores boundary rows
// every step and publishes with __threadfence + atomicExch once per 4-step
// block; consumer lane0 polls a volatile flag (short-circuited by a value
// prefetched one block earlier) and then reads boundary data with VOLATILE
// scalar loads (unhoistable past the flag poll).
// ---------------------------------------------------------------------------
__global__ void __launch_bounds__(32, 1) dtw_kernel(float* __restrict__ out) {
    const int w = blockIdx.x;
    const int lane = threadIdx.x;
    const int c0 = w * SCOLS + 4 * lane;
    const __half* gp = g_cost;
    const bool isl0 = (lane == 0);

    float t1_0 = BIGF, t1_1 = BIGF, t1_2 = BIGF, t1_3 = BIGF;
    float v30 = BIGF, v31 = BIGF, dg = BIGF;
    if (w == 0 && isl0) dg = -__half2float(g_cost[0]);   // virtual corner

    float* bndW = g_bnd + (size_t)w * NN;
    volatile const float* vb = g_bnd + (size_t)(w > 0 ? w - 1 : 0) * NN;
    int* flagW = &g_flag[w];
    volatile const int* vflag = (volatile const int*)&g_flag[w > 0 ? w - 1 : 0];
    int fpre = 0;
    float4 bb0C = make_float4(BIGF, BIGF, BIGF, BIGF), bb1C = bb0C;
    float4 bb0N = bb0C, bb1N = bb1C;

    // initial boundary block (rows 0..7) for w>0
    if (w > 0 && isl0) {
        while (*vflag < 8) { }
        bb0C = make_float4(vb[0], vb[1], vb[2], vb[3]);
        bb1C = make_float4(vb[4], vb[5], vb[6], vb[7]);
        fpre = *vflag;
    }

    // cost double-buffer: 8 uint2 (4 halfs each) = 8 rows of my 4 cols
    uint2 cbN[8], cbC[8];
    {
        int rb = -2 * lane;
        #pragma unroll
        for (int j = 0; j < 8; j++) {
            int r = rb + j; r = r < 0 ? 0 : (r > NN - 1 ? NN - 1 : r);
            cbN[j] = *(const uint2*)(gp + (size_t)r * NN + c0);
        }
    }

    for (int tb = 0; tb < TSTEPS; tb += 4) {
        #pragma unroll
        for (int j = 0; j < 8; j++) cbC[j] = cbN[j];
        {
            int rb = 2 * (tb + 4 - lane);
            #pragma unroll
            for (int j = 0; j < 8; j++) {
                int r = rb + j; r = r < 0 ? 0 : (r > NN - 1 ? NN - 1 : r);
                cbN[j] = *(const uint2*)(gp + (size_t)r * NN + c0);
            }
        }

        // prefetch NEXT block's boundary (rows 2tb+8..2tb+15)
        if (w > 0 && isl0 && 2 * (tb + 4) < NN) {
            const int need = 2 * tb + 16;
            if (fpre < need) {
                while (*vflag < need) { }
            }
            const int o = 2 * tb + 8;
            bb0N = make_float4(vb[o],     vb[o + 1], vb[o + 2], vb[o + 3]);
            bb1N = make_float4(vb[o + 4], vb[o + 5], vb[o + 6], vb[o + 7]);
            fpre = *vflag;     // for next block's short-circuit (~4 steps away)
        }

        const int rb0 = 2 * (tb - lane);

#define DTW_STEP(K, BL0, BL1)                                                 \
        {                                                                     \
            const int r0 = rb0 + 2 * (K);                                     \
            float L0 = __shfl_up_sync(FULLM, v30, 1);                         \
            float L1 = __shfl_up_sync(FULLM, v31, 1);                         \
            if (isl0) { L0 = (w == 0) ? BIGF : (BL0);                         \
                        L1 = (w == 0) ? BIGF : (BL1); }                       \
            float2 ca = __half22float2(*(const __half2*)&cbC[2*(K)].x);       \
            float2 cb = __half22float2(*(const __half2*)&cbC[2*(K)].y);       \
            float2 cc = __half22float2(*(const __half2*)&cbC[2*(K)+1].x);     \
            float2 cd = __half22float2(*(const __half2*)&cbC[2*(K)+1].y);     \
            const float c00=ca.x, c01=ca.y, c02=cb.x, c03=cb.y;               \
            const float c10=cc.x, c11=cc.y, c12=cd.x, c13=cd.y;               \
            float p0 = fminf(fmaf(2.f, c00, dg  ), t1_0 + c00);               \
            float p1 = fminf(fmaf(2.f, c01, t1_0), t1_1 + c01);               \
            float p2 = fminf(fmaf(2.f, c02, t1_1), t1_2 + c02);               \
            float p3 = fminf(fmaf(2.f, c03, t1_2), t1_3 + c03);               \
            float n00 = fminf(p0, L0  + c00);                                 \
            float n01 = fminf(p1, n00 + c01);                                 \
            float n02 = fminf(p2, n01 + c02);                                 \
            float n03 = fminf(p3, n02 + c03);                                 \
            float q0 = fminf(fmaf(2.f, c10, L0 ), n00 + c10);                 \
            float q1 = fminf(fmaf(2.f, c11, n00), n01 + c11);                 \
            float q2 = fminf(fmaf(2.f, c12, n01), n02 + c12);                 \
            float q3 = fminf(fmaf(2.f, c13, n02), n03 + c13);                 \
            float n10 = fminf(q0, L1  + c10);                                 \
            float n11 = fminf(q1, n10 + c11);                                 \
            float n12 = fminf(q2, n11 + c12);                                 \
            float n13 = fminf(q3, n12 + c13);                                 \
            if ((unsigned)r0 < NN) {                                          \
                t1_0 = n10; t1_1 = n11; t1_2 = n12; t1_3 = n13;               \
                v30 = n03; v31 = n13;                                         \
                if (lane == 31) {                                             \
                    *(float2*)(bndW + r0) = make_float2(n03, n13);            \
                    if ((K) == 3 || r0 == NN - 2) {                           \
                        __threadfence();                                      \
                        atomicExch(flagW, r0 + 2);                            \
                        if (w == NSTRIP - 1 && r0 == NN - 2) out[0] = n13;    \
                    }                                                         \
                }                                                             \
            }                                                                 \
            dg = L1;                                                          \
        }

        DTW_STEP(0, bb0C.x, bb0C.y)
        DTW_STEP(1, bb0C.z, bb0C.w)
        DTW_STEP(2, bb1C.x, bb1C.y)
        DTW_STEP(3, bb1C.z, bb1C.w)
#undef DTW_STEP

        bb0C = bb0N; bb1C = bb1N;
    }
}

// ---------------------------------------------------------------------------
extern "C" void kernel_launch(void* const* d_in, const int* in_sizes, int n_in,
                              void* d_out, int out_size) {
    const float* x = (const float*)d_in[0];
    const float* y = (const float*)d_in[1];
    float* out = (float*)d_out;

    reset_kernel<<<1, 32>>>();
    norms_kernel<<<(2 * NN + 511) / 512, 512>>>(x, y);
    cost_kernel<<<dim3(NN / 64, NN / 64), 64>>>(x, y);
    dtw_kernel<<<NSTRIP, 32>>>(out);
}

// round 9
// speedup vs baseline: 1.5945x; 1.0687x over previous
#include <cuda_runtime.h>
#include <cuda_fp16.h>
#include <math.h>

#define NN 4096
#define DD 64
#define BIGF 1e30f
#define NSTRIP 32          // strips of 128 columns, 1 warp each
#define SCOLS 128
#define TSTEPS 2080        // last active step = 2075; multiple of 16
#define FULLM 0xffffffffu

// Static device scratch
__device__ __half g_cost[(size_t)NN * NN];                 // 32 MB fp16 cost matrix
__device__ float  g_nx[NN];
__device__ float  g_ny[NN];
__device__ __align__(256) float g_bnd[NSTRIP * NN];        // right-col boundary per strip
__device__ int    g_flag[NSTRIP];                          // rows published per strip

// ---------------------------------------------------------------------------
__global__ void reset_kernel() {
    if (threadIdx.x < NSTRIP) g_flag[threadIdx.x] = 0;
}

// ---------------------------------------------------------------------------
__global__ void norms_kernel(const float* __restrict__ x, const float* __restrict__ y) {
    int i = blockIdx.x * blockDim.x + threadIdx.x;
    if (i < NN) {
        const float* p = x + (size_t)i * DD;
        float s = 0.f;
        #pragma unroll
        for (int k = 0; k < DD; k++) s += p[k] * p[k];
        g_nx[i] = s;
    } else if (i < 2 * NN) {
        int j = i - NN;
        const float* p = y + (size_t)j * DD;
        float s = 0.f;
        #pragma unroll
        for (int k = 0; k < DD; k++) s += p[k] * p[k];
        g_ny[j] = s;
    }
}

// ---------------------------------------------------------------------------
// Cost matrix: 64x64 tile per block, 64 threads, 8x8 per thread.
// ---------------------------------------------------------------------------
__global__ void __launch_bounds__(64) cost_kernel(const float* __restrict__ x,
                                                  const float* __restrict__ y) {
    __shared__ float xs[64][65];
    __shared__ float ys[64][65];

    const int I0 = blockIdx.y * 64;
    const int J0 = blockIdx.x * 64;
    const int tid = threadIdx.x;       // 0..63

    #pragma unroll 4
    for (int it = 0; it < 16; it++) {              // 16*64 float4 = 4096 floats
        int idx = (it * 64 + tid) * 4;
        int r = idx >> 6, k = idx & 63;
        float4 vx = *(const float4*)(x + (size_t)(I0 + r) * DD + k);
        float4 vy = *(const float4*)(y + (size_t)(J0 + r) * DD + k);
        xs[r][k] = vx.x; xs[r][k+1] = vx.y; xs[r][k+2] = vx.z; xs[r][k+3] = vx.w;
        ys[r][k] = vy.x; ys[r][k+1] = vy.y; ys[r][k+2] = vy.z; ys[r][k+3] = vy.w;
    }
    __syncthreads();

    const int tx = tid & 7, ty = tid >> 3;
    const int r0 = ty * 8, c0 = tx * 8;

    float acc[8][8];
    #pragma unroll
    for (int a = 0; a < 8; a++)
        #pragma unroll
        for (int b = 0; b < 8; b++) acc[a][b] = 0.f;

    #pragma unroll 4
    for (int k = 0; k < DD; k++) {
        float ra[8], rb[8];
        #pragma unroll
        for (int a = 0; a < 8; a++) ra[a] = xs[r0 + a][k];
        #pragma unroll
        for (int b = 0; b < 8; b++) rb[b] = ys[c0 + b][k];
        #pragma unroll
        for (int a = 0; a < 8; a++)
            #pragma unroll
            for (int b = 0; b < 8; b++) acc[a][b] = fmaf(ra[a], rb[b], acc[a][b]);
    }

    float nyv[8];
    #pragma unroll
    for (int b = 0; b < 8; b++) nyv[b] = g_ny[J0 + c0 + b];

    #pragma unroll
    for (int a = 0; a < 8; a++) {
        float nx = g_nx[I0 + r0 + a];
        __half2 h[4];
        #pragma unroll
        for (int b2 = 0; b2 < 4; b2++) {
            float s0 = nx + nyv[2*b2]   - 2.0f * acc[a][2*b2];
            float s1 = nx + nyv[2*b2+1] - 2.0f * acc[a][2*b2+1];
            float e0 = sqrtf(fmaxf(s0, 1e-12f));
            float e1 = sqrtf(fmaxf(s1, 1e-12f));
            h[b2] = __floats2half2_rn(e0, e1);
        }
        uint4 pk;
        pk.x = *(unsigned int*)&h[0];
        pk.y = *(unsigned int*)&h[1];
        pk.z = *(unsigned int*)&h[2];
        pk.w = *(unsigned int*)&h[3];
        *(uint4*)(g_cost + (size_t)(I0 + r0 + a) * NN + (J0 + c0)) = pk;
    }
}

// ---------------------------------------------------------------------------
// Persistent DTW: 32 strips (1 warp each), lane owns 4 cols, 2 rows per step.
// Chunked sync (32-row cadence): producer lane31 plain-stores boundary rows
// every step, fence+atomicExch once per 32 rows (16 steps). Consumer lane0
// polls once per 16-step superblock (short-circuited by prefetched flag) and
// volatile-loads the NEXT 32 boundary rows into a register queue, one
// superblock (~1100cyc) before use. Cost loads prefetched 2 blocks ahead.
// ---------------------------------------------------------------------------
__global__ void __launch_bounds__(32, 1) dtw_kernel(float* __restrict__ out) {
    const int w = blockIdx.x;
    const int lane = threadIdx.x;
    const int c0 = w * SCOLS + 4 * lane;
    const __half* gp = g_cost;
    const bool isl0 = (lane == 0);

    float t1_0 = BIGF, t1_1 = BIGF, t1_2 = BIGF, t1_3 = BIGF;
    float v30 = BIGF, v31 = BIGF, dg = BIGF;
    if (w == 0 && isl0) dg = -__half2float(g_cost[0]);   // virtual corner

    float* bndW = g_bnd + (size_t)w * NN;
    volatile const float* vb = g_bnd + (size_t)(w > 0 ? w - 1 : 0) * NN;
    int* flagW = &g_flag[w];
    volatile const int* vflag = (volatile const int*)&g_flag[w > 0 ? w - 1 : 0];
    int fpre = 0;

    float4 bq[8], bn[8];                 // boundary queues: current / next chunk
    #pragma unroll
    for (int i = 0; i < 8; i++) { bq[i] = make_float4(BIGF,BIGF,BIGF,BIGF); bn[i] = bq[i]; }

    // initial chunk (rows 0..31) for w>0
    if (w > 0 && isl0) {
        while (*vflag < 32) { }
        #pragma unroll
        for (int i = 0; i < 8; i++)
            bq[i] = make_float4(vb[4*i], vb[4*i+1], vb[4*i+2], vb[4*i+3]);
        fpre = *vflag;
    }

    // cost ring: 3-deep, each = 8 uint2 (8 rows of my 4 cols), 2 blocks ahead
    uint2 cbC[8], cbA[8], cbB[8];
    {
        int rb = -2 * lane;
        #pragma unroll
        for (int j = 0; j < 8; j++) {
            int r = rb + j; r = r < 0 ? 0 : (r > NN - 1 ? NN - 1 : r);
            cbC[j] = *(const uint2*)(gp + (size_t)r * NN + c0);
        }
        rb = 2 * (4 - lane);
        #pragma unroll
        for (int j = 0; j < 8; j++) {
            int r = rb + j; r = r < 0 ? 0 : (r > NN - 1 ? NN - 1 : r);
            cbA[j] = *(const uint2*)(gp + (size_t)r * NN + c0);
        }
    }

    for (int sb = 0; sb < TSTEPS; sb += 16) {
        // poll + load NEXT chunk (rows 2sb+32 .. 2sb+63), used at superblock sb+16
        if (w > 0 && isl0 && 2 * sb + 32 < NN) {
            const int need = 2 * sb + 64;          // max 4096, never exceeds
            if (fpre < need) {
                while (*vflag < need) { }
            }
            const int o = 2 * sb + 32;
            #pragma unroll
            for (int i = 0; i < 8; i++)
                bn[i] = make_float4(vb[o+4*i], vb[o+4*i+1], vb[o+4*i+2], vb[o+4*i+3]);
            fpre = *vflag;
        }

        #pragma unroll
        for (int b = 0; b < 4; b++) {
            const int tb = sb + 4 * b;

            // cost ring: load block tb+8 into cbB (2 blocks ahead)
            {
                int rb = 2 * (tb + 8 - lane);
                #pragma unroll
                for (int j = 0; j < 8; j++) {
                    int r = rb + j; r = r < 0 ? 0 : (r > NN - 1 ? NN - 1 : r);
                    cbB[j] = *(const uint2*)(gp + (size_t)r * NN + c0);
                }
            }

            const int rb0 = 2 * (tb - lane);

#define DTW_STEP(K, BL0, BL1)                                                 \
            {                                                                 \
                const int r0 = rb0 + 2 * (K);                                 \
                float L0 = __shfl_up_sync(FULLM, v30, 1);                     \
                float L1 = __shfl_up_sync(FULLM, v31, 1);                     \
                if (isl0) { L0 = (w == 0) ? BIGF : (BL0);                     \
                            L1 = (w == 0) ? BIGF : (BL1); }                   \
                float2 ca = __half22float2(*(const __half2*)&cbC[2*(K)].x);   \
                float2 cb = __half22float2(*(const __half2*)&cbC[2*(K)].y);   \
                float2 cc = __half22float2(*(const __half2*)&cbC[2*(K)+1].x); \
                float2 cd = __half22float2(*(const __half2*)&cbC[2*(K)+1].y); \
                const float c00=ca.x, c01=ca.y, c02=cb.x, c03=cb.y;           \
                const float c10=cc.x, c11=cc.y, c12=cd.x, c13=cd.y;           \
                float p0 = fminf(fmaf(2.f, c00, dg  ), t1_0 + c00);           \
                float p1 = fminf(fmaf(2.f, c01, t1_0), t1_1 + c01);           \
                float p2 = fminf(fmaf(2.f, c02, t1_1), t1_2 + c02);           \
                float p3 = fminf(fmaf(2.f, c03, t1_2), t1_3 + c03);           \
                float n00 = fminf(p0, L0  + c00);                             \
                float n01 = fminf(p1, n00 + c01);                             \
                float n02 = fminf(p2, n01 + c02);                             \
                float n03 = fminf(p3, n02 + c03);                             \
                float q0 = fminf(fmaf(2.f, c10, L0 ), n00 + c10);             \
                float q1 = fminf(fmaf(2.f, c11, n00), n01 + c11);             \
                float q2 = fminf(fmaf(2.f, c12, n01), n02 + c12);             \
                float q3 = fminf(fmaf(2.f, c13, n02), n03 + c13);             \
                float n10 = fminf(q0, L1  + c10);                             \
                float n11 = fminf(q1, n10 + c11);                             \
                float n12 = fminf(q2, n11 + c12);                             \
                float n13 = fminf(q3, n12 + c13);                             \
                if ((unsigned)r0 < NN) {                                      \
                    t1_0 = n10; t1_1 = n11; t1_2 = n12; t1_3 = n13;           \
                    v30 = n03; v31 = n13;                                     \
                    if (lane == 31) {                                         \
                        *(float2*)(bndW + r0) = make_float2(n03, n13);        \
                        if (((r0 + 2) & 31) == 0) {                           \
                            __threadfence();                                  \
                            atomicExch(flagW, r0 + 2);                        \
                            if (w == NSTRIP - 1 && r0 == NN - 2)              \
                                out[0] = n13;                                 \
                        }                                                     \
                    }                                                         \
                }                                                             \
                dg = L1;                                                      \
            }

            DTW_STEP(0, bq[2*b].x,     bq[2*b].y)
            DTW_STEP(1, bq[2*b].z,     bq[2*b].w)
            DTW_STEP(2, bq[2*b + 1].x, bq[2*b + 1].y)
            DTW_STEP(3, bq[2*b + 1].z, bq[2*b + 1].w)
#undef DTW_STEP

            // rotate cost ring
            #pragma unroll
            for (int j = 0; j < 8; j++) { cbC[j] = cbA[j]; cbA[j] = cbB[j]; }
        }

        // rotate boundary queue
        #pragma unroll
        for (int i = 0; i < 8; i++) bq[i] = bn[i];
    }
}

// ---------------------------------------------------------------------------
extern "C" void kernel_launch(void* const* d_in, const int* in_sizes, int n_in,
                              void* d_out, int out_size) {
    const float* x = (const float*)d_in[0];
    const float* y = (const float*)d_in[1];
    float* out = (float*)d_out;

    reset_kernel<<<1, 32>>>();
    norms_kernel<<<(2 * NN + 511) / 512, 512>>>(x, y);
    cost_kernel<<<dim3(NN / 64, NN / 64), 64>>>(x, y);
    dtw_kernel<<<NSTRIP, 32>>>(out);
}

// round 10
// speedup vs baseline: 3.8036x; 2.3854x over previous
#include <cuda_runtime.h>
#include <cuda_fp16.h>
#include <math.h>

#define NN 4096
#define DD 64
#define BIGF 1e30f
#define NWARP 64           // 64 strips of 64 columns, 1 warp each
#define TSTEPS 4128        // 4096 + 32 (lane skew); 129 chunks of 32
#define FULLM 0xffffffffu

// Static device scratch
__device__ __half g_cost[(size_t)NN * NN];   // 32 MB fp16 cost matrix
__device__ float  g_nx[NN];
__device__ float  g_ny[NN];
__device__ float  g_bnd[NWARP * NN];         // right-column boundary per strip
__device__ int    g_flag[NWARP];             // rows completed per strip

// predicated single store — avoids BSSY/BSYNC divergence envelope
__device__ __forceinline__ void st_pred(float* p, float v, int pred) {
    asm volatile("{ .reg .pred p0; setp.ne.s32 p0, %2, 0; @p0 st.global.f32 [%0], %1; }"
                 :: "l"(p), "f"(v), "r"(pred) : "memory");
}

// ---------------------------------------------------------------------------
__global__ void reset_kernel() {
    if (threadIdx.x < NWARP) g_flag[threadIdx.x] = 0;
}

// ---------------------------------------------------------------------------
__global__ void norms_kernel(const float* __restrict__ x, const float* __restrict__ y) {
    int i = blockIdx.x * blockDim.x + threadIdx.x;
    if (i < NN) {
        const float* p = x + (size_t)i * DD;
        float s = 0.f;
        #pragma unroll
        for (int k = 0; k < DD; k++) s += p[k] * p[k];
        g_nx[i] = s;
    } else if (i < 2 * NN) {
        int j = i - NN;
        const float* p = y + (size_t)j * DD;
        float s = 0.f;
        #pragma unroll
        for (int k = 0; k < DD; k++) s += p[k] * p[k];
        g_ny[j] = s;
    }
}

// ---------------------------------------------------------------------------
// Cost matrix: 64x64 tile per block, 64 threads, 8x8 per thread.
// ---------------------------------------------------------------------------
__global__ void __launch_bounds__(64) cost_kernel(const float* __restrict__ x,
                                                  const float* __restrict__ y) {
    __shared__ float xs[64][65];
    __shared__ float ys[64][65];

    const int I0 = blockIdx.y * 64;
    const int J0 = blockIdx.x * 64;
    const int tid = threadIdx.x;       // 0..63

    #pragma unroll 4
    for (int it = 0; it < 16; it++) {              // 16*64 float4 = 4096 floats
        int idx = (it * 64 + tid) * 4;
        int r = idx >> 6, k = idx & 63;
        float4 vx = *(const float4*)(x + (size_t)(I0 + r) * DD + k);
        float4 vy = *(const float4*)(y + (size_t)(J0 + r) * DD + k);
        xs[r][k] = vx.x; xs[r][k+1] = vx.y; xs[r][k+2] = vx.z; xs[r][k+3] = vx.w;
        ys[r][k] = vy.x; ys[r][k+1] = vy.y; ys[r][k+2] = vy.z; ys[r][k+3] = vy.w;
    }
    __syncthreads();

    const int tx = tid & 7, ty = tid >> 3;
    const int r0 = ty * 8, c0 = tx * 8;

    float acc[8][8];
    #pragma unroll
    for (int a = 0; a < 8; a++)
        #pragma unroll
        for (int b = 0; b < 8; b++) acc[a][b] = 0.f;

    #pragma unroll 4
    for (int k = 0; k < DD; k++) {
        float ra[8], rb[8];
        #pragma unroll
        for (int a = 0; a < 8; a++) ra[a] = xs[r0 + a][k];
        #pragma unroll
        for (int b = 0; b < 8; b++) rb[b] = ys[c0 + b][k];
        #pragma unroll
        for (int a = 0; a < 8; a++)
            #pragma unroll
            for (int b = 0; b < 8; b++) acc[a][b] = fmaf(ra[a], rb[b], acc[a][b]);
    }

    float nyv[8];
    #pragma unroll
    for (int b = 0; b < 8; b++) nyv[b] = g_ny[J0 + c0 + b];

    #pragma unroll
    for (int a = 0; a < 8; a++) {
        float nx = g_nx[I0 + r0 + a];
        __half2 h[4];
        #pragma unroll
        for (int b2 = 0; b2 < 4; b2++) {
            float s0 = nx + nyv[2*b2]   - 2.0f * acc[a][2*b2];
            float s1 = nx + nyv[2*b2+1] - 2.0f * acc[a][2*b2+1];
            float e0 = sqrtf(fmaxf(s0, 1e-12f));
            float e1 = sqrtf(fmaxf(s1, 1e-12f));
            h[b2] = __floats2half2_rn(e0, e1);
        }
        uint4 pk;
        pk.x = *(unsigned int*)&h[0];
        pk.y = *(unsigned int*)&h[1];
        pk.z = *(unsigned int*)&h[2];
        pk.w = *(unsigned int*)&h[3];
        *(uint4*)(g_cost + (size_t)(I0 + r0 + a) * NN + (J0 + c0)) = pk;
    }
}

// ---------------------------------------------------------------------------
// Persistent DTW (round-2 dataflow, branchless inner loop):
// 64 strips x 1 warp; lane owns 2 adjacent columns; at step ss computes row
// r = ss - lane. Neighbor values via shfl; lane0's left boundary comes from a
// 32-row chunk loaded cooperatively (1 volatile load/lane) and broadcast by
// shfl. Chunk poll + publish are per-chunk uniform branches; everything
// inside the 32 unrolled steps is select/predicate-based (no BSSY).
// ---------------------------------------------------------------------------
__global__ void __launch_bounds__(32, 1) dtw_kernel(float* __restrict__ out) {
    const int w = blockIdx.x;
    const int lane = threadIdx.x;
    const int cidx = (w * 64) / 2 + lane;    // __half2 column index (2 cols/lane)
    const __half2* cptr = (const __half2*)g_cost;

    // state: v1c0/v1c1 = D[prev row][c0/c1]; v2c1 = D[prev-1 row][c1]
    float v1c0 = BIGF, v1c1 = BIGF, v2c1 = BIGF;
    float prev0 = BIGF;                       // lane0: D[r-1][base-1]
    if (w == 0 && lane == 0)
        prev0 = -__half2float(((const __half*)g_cost)[0]);  // virtual corner seed

    float* bndW = g_bnd + (size_t)w * NN;
    const volatile float* bndp = g_bnd + (size_t)(w > 0 ? w - 1 : 0) * NN;
    const volatile int* vflag = (const volatile int*)&g_flag[w > 0 ? w - 1 : 0];
    int* flagW = &g_flag[w];

    // cost prefetch ring (8 steps ahead)
    __half2 cp[8];
    #pragma unroll
    for (int k = 0; k < 8; k++) {
        int r = k - lane; r = r < 0 ? 0 : r;
        cp[k] = cptr[(size_t)r * (NN / 2) + cidx];
    }

    for (int cs = 0; cs < TSTEPS; cs += 32) {
        // chunk poll + cooperative boundary load (uniform branch, 1/32 steps)
        float bval = BIGF;
        if (w > 0 && cs < NN) {
            while (*vflag < cs + 32) { }
            bval = bndp[cs + lane];
        }

        #pragma unroll
        for (int k = 0; k < 32; k++) {
            const int ss = cs + k;
            const int r = ss - lane;

            float lfs = __shfl_up_sync(FULLM, v1c1, 1);
            float dgs = __shfl_up_sync(FULLM, v2c1, 1);
            float bb  = __shfl_sync(FULLM, bval, k);

            const bool l0 = (lane == 0);
            float lfv = l0 ? bb : lfs;
            float dgv = l0 ? prev0 : dgs;
            prev0 = bb;

            float2 cc = __half22float2(cp[k & 7]);

            // prefetch cost for step ss+8 (off the dependency chain)
            int rl = ss + 8 - lane;
            rl = rl < 0 ? 0 : (rl > NN - 1 ? NN - 1 : rl);
            __half2 nxt = cptr[(size_t)rl * (NN / 2) + cidx];

            float n0 = fminf(fminf(fmaf(2.f, cc.x, dgv), v1c0 + cc.x), lfv + cc.x);
            float n1 = fminf(fminf(fmaf(2.f, cc.y, v1c0), v1c1 + cc.y), n0 + cc.y);

            const bool act = ((unsigned)r < NN);
            v2c1 = act ? v1c1 : v2c1;
            v1c0 = act ? n0 : v1c0;
            v1c1 = act ? n1 : v1c1;

            // boundary store (lane31 only, in-range) — predicated, no branch
            int rcl = r < 0 ? 0 : (r > NN - 1 ? NN - 1 : r);
            st_pred(bndW + rcl, n1, (int)(act && lane == 31));

            cp[k & 7] = nxt;
        }

        // publish: lane31 has completed rows 0..cs  =>  flag = cs+1
        if (lane == 31) {
            __threadfence();
            atomicExch(flagW, cs + 1);
        }
    }

    if (w == NWARP - 1 && lane == 31)
        out[0] = v1c1;          // D[4095][4095]
}

// ---------------------------------------------------------------------------
extern "C" void kernel_launch(void* const* d_in, const int* in_sizes, int n_in,
                              void* d_out, int out_size) {
    const float* x = (const float*)d_in[0];
    const float* y = (const float*)d_in[1];
    float* out = (float*)d_out;

    reset_kernel<<<1, 64>>>();
    norms_kernel<<<(2 * NN + 511) / 512, 512>>>(x, y);
    cost_kernel<<<dim3(NN / 64, NN / 64), 64>>>(x, y);
    dtw_kernel<<<NWARP, 32>>>(out);
}

// round 11
// speedup vs baseline: 4.3067x; 1.1323x over previous
#include <cuda_runtime.h>
#include <cuda_fp16.h>
#include <math.h>

#define NN 4096
#define DD 64
#define BIGF 1e30f
#define NWARP 64           // 64 strips of 64 columns, 1 warp each
#define TSTEPS 4128        // 4096 + 32 (lane skew); 129 chunks of 32
#define FULLM 0xffffffffu

// Diagonal-major cost storage: g_costd[((w*TSTEPS)+ss)*32 + lane] holds the
// half2 cost (c[r][c0], c[r][c0+1]) for r = ss - lane, c0 = w*64 + 2*lane.
// DTW reads one coalesced 128B line per warp per step.
__device__ __half2 g_costd[(size_t)NWARP * TSTEPS * 32];   // ~33.8 MB
__device__ float  g_nx[NN];
__device__ float  g_ny[NN];
__device__ float  g_c00;                     // c[0][0] for the virtual corner
__device__ float  g_bnd[NWARP * NN];         // right-column boundary per strip
__device__ int    g_flag[NWARP];             // rows completed per strip

// predicated single store — avoids BSSY/BSYNC divergence envelope
__device__ __forceinline__ void st_pred(float* p, float v, int pred) {
    asm volatile("{ .reg .pred p0; setp.ne.s32 p0, %2, 0; @p0 st.global.f32 [%0], %1; }"
                 :: "l"(p), "f"(v), "r"(pred) : "memory");
}

// ---------------------------------------------------------------------------
__global__ void reset_kernel() {
    if (threadIdx.x < NWARP) g_flag[threadIdx.x] = 0;
}

// ---------------------------------------------------------------------------
__global__ void norms_kernel(const float* __restrict__ x, const float* __restrict__ y) {
    int i = blockIdx.x * blockDim.x + threadIdx.x;
    if (i < NN) {
        const float* p = x + (size_t)i * DD;
        float s = 0.f;
        #pragma unroll
        for (int k = 0; k < DD; k++) s += p[k] * p[k];
        g_nx[i] = s;
    } else if (i < 2 * NN) {
        int j = i - NN;
        const float* p = y + (size_t)j * DD;
        float s = 0.f;
        #pragma unroll
        for (int k = 0; k < DD; k++) s += p[k] * p[k];
        g_ny[j] = s;
    }
}

// ---------------------------------------------------------------------------
// Cost matrix: 64x64 tile per block (tile == strip width), 64 threads,
// 8x8 per thread. Results written directly in diagonal-major layout.
// ---------------------------------------------------------------------------
__global__ void __launch_bounds__(64) cost_kernel(const float* __restrict__ x,
                                                  const float* __restrict__ y) {
    __shared__ float xs[64][65];
    __shared__ float ys[64][65];

    const int I0 = blockIdx.y * 64;
    const int w  = blockIdx.x;          // strip id == column tile id
    const int J0 = w * 64;
    const int tid = threadIdx.x;        // 0..63

    #pragma unroll 4
    for (int it = 0; it < 16; it++) {               // 16*64 float4 = 4096 floats
        int idx = (it * 64 + tid) * 4;
        int r = idx >> 6, k = idx & 63;
        float4 vx = *(const float4*)(x + (size_t)(I0 + r) * DD + k);
        float4 vy = *(const float4*)(y + (size_t)(J0 + r) * DD + k);
        xs[r][k] = vx.x; xs[r][k+1] = vx.y; xs[r][k+2] = vx.z; xs[r][k+3] = vx.w;
        ys[r][k] = vy.x; ys[r][k+1] = vy.y; ys[r][k+2] = vy.z; ys[r][k+3] = vy.w;
    }
    __syncthreads();

    const int tx = tid & 7, ty = tid >> 3;
    const int r0 = ty * 8, c0 = tx * 8;

    float acc[8][8];
    #pragma unroll
    for (int a = 0; a < 8; a++)
        #pragma unroll
        for (int b = 0; b < 8; b++) acc[a][b] = 0.f;

    #pragma unroll 4
    for (int k = 0; k < DD; k++) {
        float ra[8], rb[8];
        #pragma unroll
        for (int a = 0; a < 8; a++) ra[a] = xs[r0 + a][k];
        #pragma unroll
        for (int b = 0; b < 8; b++) rb[b] = ys[c0 + b][k];
        #pragma unroll
        for (int a = 0; a < 8; a++)
            #pragma unroll
            for (int b = 0; b < 8; b++) acc[a][b] = fmaf(ra[a], rb[b], acc[a][b]);
    }

    float nyv[8];
    #pragma unroll
    for (int b = 0; b < 8; b++) nyv[b] = g_ny[J0 + c0 + b];

    #pragma unroll
    for (int a = 0; a < 8; a++) {
        const int i = I0 + r0 + a;
        float nx = g_nx[i];
        #pragma unroll
        for (int b2 = 0; b2 < 4; b2++) {
            float s0 = nx + nyv[2*b2]   - 2.0f * acc[a][2*b2];
            float s1 = nx + nyv[2*b2+1] - 2.0f * acc[a][2*b2+1];
            float e0 = sqrtf(fmaxf(s0, 1e-12f));
            float e1 = sqrtf(fmaxf(s1, 1e-12f));
            const int lane = tx * 4 + b2;          // lane owning these 2 cols
            const int ss = i + lane;               // diagonal step index
            g_costd[((size_t)w * TSTEPS + ss) * 32 + lane] = __floats2half2_rn(e0, e1);
        }
    }

    if (w == 0 && I0 == 0 && tid == 0) {
        float sq = g_nx[0] + g_ny[0] - 2.0f * acc[0][0];   // tid0 owns (0,0)
        g_c00 = sqrtf(fmaxf(sq, 1e-12f));
    }
}

// ---------------------------------------------------------------------------
// Persistent DTW (round-10 dataflow, diagonal-major cost loads):
// 64 strips x 1 warp; lane owns 2 adjacent columns; at step ss computes row
// r = ss - lane. One coalesced 128B cost load per warp per step.
// ---------------------------------------------------------------------------
__global__ void __launch_bounds__(32, 1) dtw_kernel(float* __restrict__ out) {
    const int w = blockIdx.x;
    const int lane = threadIdx.x;
    const __half2* cptr = g_costd + (size_t)w * TSTEPS * 32;

    // state: v1c0/v1c1 = D[prev row][c0/c1]; v2c1 = D[prev-1 row][c1]
    float v1c0 = BIGF, v1c1 = BIGF, v2c1 = BIGF;
    float prev0 = BIGF;                       // lane0: D[r-1][base-1]
    if (w == 0 && lane == 0)
        prev0 = -g_c00;                       // virtual corner seed

    float* bndW = g_bnd + (size_t)w * NN;
    const volatile float* bndp = g_bnd + (size_t)(w > 0 ? w - 1 : 0) * NN;
    const volatile int* vflag = (const volatile int*)&g_flag[w > 0 ? w - 1 : 0];
    int* flagW = &g_flag[w];

    // cost prefetch ring (8 steps ahead), coalesced
    __half2 cp[8];
    #pragma unroll
    for (int k = 0; k < 8; k++)
        cp[k] = cptr[(size_t)k * 32 + lane];

    for (int cs = 0; cs < TSTEPS; cs += 32) {
        // chunk poll + cooperative boundary load (uniform branch, 1/32 steps)
        float bval = BIGF;
        if (w > 0 && cs < NN) {
            while (*vflag < cs + 32) { }
            bval = bndp[cs + lane];
        }

        #pragma unroll
        for (int k = 0; k < 32; k++) {
            const int ss = cs + k;
            const int r = ss - lane;

            float lfs = __shfl_up_sync(FULLM, v1c1, 1);
            float dgs = __shfl_up_sync(FULLM, v2c1, 1);
            float bb  = __shfl_sync(FULLM, bval, k);

            const bool l0 = (lane == 0);
            float lfv = l0 ? bb : lfs;
            float dgv = l0 ? prev0 : dgs;
            prev0 = bb;

            float2 cc = __half22float2(cp[k & 7]);

            // prefetch cost for step ss+8 (coalesced, off the dependency chain)
            int sl = ss + 8; sl = sl < TSTEPS ? sl : TSTEPS - 1;
            __half2 nxt = cptr[(size_t)sl * 32 + lane];

            float n0 = fminf(fminf(fmaf(2.f, cc.x, dgv), v1c0 + cc.x), lfv + cc.x);
            float n1 = fminf(fminf(fmaf(2.f, cc.y, v1c0), v1c1 + cc.y), n0 + cc.y);

            const bool act = ((unsigned)r < NN);
            v2c1 = act ? v1c1 : v2c1;
            v1c0 = act ? n0 : v1c0;
            v1c1 = act ? n1 : v1c1;

            // boundary store (lane31 only, in-range) — predicated, no branch
            int rcl = r < 0 ? 0 : (r > NN - 1 ? NN - 1 : r);
            st_pred(bndW + rcl, n1, (int)(act && lane == 31));

            cp[k & 7] = nxt;
        }

        // publish: flag = cs+1 (lane31 has completed rows 0..cs)
        if (lane == 31) {
            __threadfence();
            atomicExch(flagW, cs + 1);
        }
    }

    if (w == NWARP - 1 && lane == 31)
        out[0] = v1c1;          // D[4095][4095]
}

// ---------------------------------------------------------------------------
extern "C" void kernel_launch(void* const* d_in, const int* in_sizes, int n_in,
                              void* d_out, int out_size) {
    const float* x = (const float*)d_in[0];
    const float* y = (const float*)d_in[1];
    float* out = (float*)d_out;

    reset_kernel<<<1, 64>>>();
    norms_kernel<<<(2 * NN + 511) / 512, 512>>>(x, y);
    cost_kernel<<<dim3(NN / 64, NN / 64), 64>>>(x, y);
    dtw_kernel<<<NWARP, 32>>>(out);
}